// round 15
// baseline (speedup 1.0000x reference)
#include <cuda_runtime.h>
#include <cuda_fp16.h>
#include <stdint.h>

#define NMAX 100000
#define CAP  64   // max in-degree bucket (Poisson(10): P(deg>64) ~ 1e-40)

// ---------------- scratch (static device globals; no allocation) ----------------
__device__ int g_cnt[NMAX];
__device__ int g_slots[(size_t)NMAX * CAP];
__device__ __half g_XSh[(size_t)NMAX * 128];
__device__ __half g_XNh[(size_t)NMAX * 128];
__device__ __half g_Hh [(size_t)NMAX * 128];
__device__ __half g_HSh[(size_t)NMAX * 64];
__device__ __half g_HNh[(size_t)NMAX * 64];
__device__ __half g_Wt1[256 * 128];
__device__ __half g_Wt2[128 * 128];

__device__ __forceinline__ void addf32x2(float2& a, float2 b) {
    unsigned long long ua = reinterpret_cast<unsigned long long&>(a);
    unsigned long long ub = reinterpret_cast<unsigned long long&>(b);
    asm("add.rn.f32x2 %0, %0, %1;" : "+l"(ua) : "l"(ub));
    a = reinterpret_cast<float2&>(ua);
}
__device__ __forceinline__ uint32_t smem_u32(const void* p) {
    uint32_t a;
    asm("{ .reg .u64 t; cvta.to.shared.u64 t, %1; cvt.u32.u64 %0, t; }" : "=r"(a) : "l"(p));
    return a;
}
__device__ __forceinline__ void ldsm_x4(uint32_t r[4], uint32_t addr) {
    asm volatile("ldmatrix.sync.aligned.m8n8.x4.shared.b16 {%0,%1,%2,%3}, [%4];"
                 : "=r"(r[0]), "=r"(r[1]), "=r"(r[2]), "=r"(r[3]) : "r"(addr));
}

// ---------------- prep: both weight transposes ----------------
__global__ void k_prep(const float* __restrict__ Ws1, const float* __restrict__ Wn1,
                       const float* __restrict__ Ws2, const float* __restrict__ Wn2) {
    int b = blockIdx.x, tid = threadIdx.x;
    if (b < 128) {                                // Wt1: 256*128 elems
        int idx = b * 256 + tid;
        int k = idx >> 8, nn = idx & 255;
        float v = (nn < 128) ? Ws1[(size_t)k * 128 + nn] : Wn1[(size_t)k * 128 + (nn - 128)];
        g_Wt1[(size_t)nn * 128 + k] = __float2half(v);
    } else {                                      // Wt2: 128*128 elems
        int idx = (b - 128) * 256 + tid;
        int k = idx >> 7, nn = idx & 127;
        float v = (nn < 64) ? Ws2[(size_t)k * 64 + nn] : Wn2[(size_t)k * 64 + (nn - 64)];
        g_Wt2[(size_t)nn * 128 + k] = __float2half(v);
    }
}

// ---------------- scatter: 4 edges per thread via int4 ----------------
__global__ void k_scatter(const int* __restrict__ src, const int* __restrict__ dst, int e) {
    const int nq = e >> 2;
    const int4* s4 = reinterpret_cast<const int4*>(src);
    const int4* d4 = reinterpret_cast<const int4*>(dst);
    for (int q = blockIdx.x * blockDim.x + threadIdx.x; q < nq; q += gridDim.x * blockDim.x) {
        int4 s = s4[q];
        int4 d = d4[q];
        int p;
        p = atomicAdd(&g_cnt[d.x], 1); if (p < CAP) g_slots[(size_t)d.x * CAP + p] = s.x;
        p = atomicAdd(&g_cnt[d.y], 1); if (p < CAP) g_slots[(size_t)d.y * CAP + p] = s.y;
        p = atomicAdd(&g_cnt[d.z], 1); if (p < CAP) g_slots[(size_t)d.z * CAP + p] = s.z;
        p = atomicAdd(&g_cnt[d.w], 1); if (p < CAP) g_slots[(size_t)d.w * CAP + p] = s.w;
    }
    if (blockIdx.x == 0 && threadIdx.x == 0) {
        for (int i = nq * 4; i < e; i++) {
            int d = dst[i];
            int p = atomicAdd(&g_cnt[d], 1);
            if (p < CAP) g_slots[(size_t)d * CAP + p] = src[i];
        }
    }
}

// ---------------- fp16 mma.sync GEMM with ldmatrix, double-buffered smem ----------------
__device__ __forceinline__ void mma_f16(float c[4], const uint32_t a[4], const uint32_t b[2]) {
    asm volatile(
        "mma.sync.aligned.m16n8k16.row.col.f32.f16.f16.f32 "
        "{%0,%1,%2,%3}, {%4,%5,%6,%7}, {%8,%9}, {%0,%1,%2,%3};\n"
        : "+f"(c[0]), "+f"(c[1]), "+f"(c[2]), "+f"(c[3])
        : "r"(a[0]), "r"(a[1]), "r"(a[2]), "r"(a[3]), "r"(b[0]), "r"(b[1]));
}

// [C1h|C2h] = A[n x 128] @ Wt^T. CTA 128(M) x NT(N), K=128, BK=32, 2-stage smem pipeline.
template <int NT, int THREADS, int WM, int MFRAG, typename TA>
__global__ void __launch_bounds__(THREADS, 1)
k_gemm_f16(const TA* __restrict__ A, const __half* __restrict__ Wt,
           __half* __restrict__ C1, __half* __restrict__ C2, int n) {
    constexpr int BK = 32;
    constexpr int NH = NT / 2;
    constexpr int NWARPS = THREADS / 32;
    constexpr int WN = NWARPS / WM;
    constexpr int NFRAG = NT / (WN * 8);
    constexpr int S32 = 20;
    constexpr int PA = 128 * BK / 8 / THREADS;
    constexpr int PB = NT * BK / 8 / THREADS;
    constexpr int NTILES = 128 / BK;
    constexpr int A_WORDS = 128 * S32;      // per buffer
    constexpr int B_WORDS = NT * S32;

    extern __shared__ uint32_t sm[];
    uint32_t* As = sm;                       // [2][A_WORDS]
    uint32_t* Bs = sm + 2 * A_WORDS;         // [2][B_WORDS]

    const int tid = threadIdx.x;
    const int lane = tid & 31, wid = tid >> 5;
    const int wm = wid % WM, wn = wid / WM;
    const int m0 = wm * (MFRAG * 16);
    const int n0 = wn * (NFRAG * 8);
    const int g = lane >> 2, t = lane & 3;
    const int rbase = blockIdx.x * 128;

    const uint32_t as_b = smem_u32(As), bs_b = smem_u32(Bs);
    const int aRow = m0 + ((lane >> 3) & 1) * 8 + (lane & 7);
    const int aK = (lane >> 4) * 16;
    const uint32_t aAddr = as_b + aRow * 80 + aK;
    const int bRow = n0 + (lane >> 4) * 8 + (lane & 7);
    const int bK = ((lane >> 3) & 1) * 16;
    const uint32_t bAddr = bs_b + bRow * 80 + bK;

    float acc[MFRAG][NFRAG][4];
#pragma unroll
    for (int mf = 0; mf < MFRAG; mf++)
#pragma unroll
        for (int nf = 0; nf < NFRAG; nf++)
#pragma unroll
            for (int j = 0; j < 4; j++) acc[mf][nf][j] = 0.f;

    uint4 pa[PA], pb[PB];

    auto load_a = [&](int kk) {
#pragma unroll
        for (int i = 0; i < PA; i++) {
            int idx = tid + i * THREADS;
            int row = idx >> 2, kg = idx & 3;
            int r = rbase + row;
            if (sizeof(TA) == 4) {
                const float* Af = reinterpret_cast<const float*>(A);
                float4 f0, f1;
                if (r < n) {
                    f0 = *reinterpret_cast<const float4*>(&Af[(size_t)r * 128 + kk + kg * 8]);
                    f1 = *reinterpret_cast<const float4*>(&Af[(size_t)r * 128 + kk + kg * 8 + 4]);
                } else {
                    f0 = f1 = make_float4(0.f, 0.f, 0.f, 0.f);
                }
                __half2 h0 = __floats2half2_rn(f0.x, f0.y);
                __half2 h1 = __floats2half2_rn(f0.z, f0.w);
                __half2 h2 = __floats2half2_rn(f1.x, f1.y);
                __half2 h3 = __floats2half2_rn(f1.z, f1.w);
                pa[i] = make_uint4(reinterpret_cast<uint32_t&>(h0), reinterpret_cast<uint32_t&>(h1),
                                   reinterpret_cast<uint32_t&>(h2), reinterpret_cast<uint32_t&>(h3));
            } else {
                const __half* Ah = reinterpret_cast<const __half*>(A);
                pa[i] = (r < n) ? *reinterpret_cast<const uint4*>(&Ah[(size_t)r * 128 + kk + kg * 8])
                                : make_uint4(0u, 0u, 0u, 0u);
            }
        }
    };
    auto load_b = [&](int kk) {
#pragma unroll
        for (int i = 0; i < PB; i++) {
            int idx = tid + i * THREADS;
            int nn = idx >> 2, kg = idx & 3;
            pb[i] = *reinterpret_cast<const uint4*>(&Wt[(size_t)nn * 128 + kk + kg * 8]);
        }
    };
    auto store_tile = [&](int buf) {
#pragma unroll
        for (int i = 0; i < PA; i++) {
            int idx = tid + i * THREADS;
            int row = idx >> 2, kg = idx & 3;
            *reinterpret_cast<uint4*>(&As[buf * A_WORDS + row * S32 + kg * 4]) = pa[i];
        }
#pragma unroll
        for (int i = 0; i < PB; i++) {
            int idx = tid + i * THREADS;
            int nn = idx >> 2, kg = idx & 3;
            *reinterpret_cast<uint4*>(&Bs[buf * B_WORDS + nn * S32 + kg * 4]) = pb[i];
        }
    };

    load_a(0);
    load_b(0);
    store_tile(0);
    __syncthreads();

    for (int tt = 0; tt < NTILES; tt++) {
        const int cur = tt & 1;
        const uint32_t aOff = cur * (A_WORDS * 4);
        const uint32_t bOff = cur * (B_WORDS * 4);

        if (tt + 1 < NTILES) {          // issue next-tile gmem loads early
            load_a((tt + 1) * BK);
            load_b((tt + 1) * BK);
        }

        // compute current buffer (hides the gmem load latency)
#pragma unroll
        for (int ks = 0; ks < BK; ks += 16) {
            uint32_t afr[MFRAG][4];
#pragma unroll
            for (int mf = 0; mf < MFRAG; mf++)
                ldsm_x4(afr[mf], aAddr + aOff + mf * 16 * 80 + ks * 2);
            uint32_t bfr[NFRAG][2];
#pragma unroll
            for (int nf2 = 0; nf2 < NFRAG / 2; nf2++) {
                uint32_t r[4];
                ldsm_x4(r, bAddr + bOff + nf2 * 16 * 80 + ks * 2);
                bfr[2 * nf2][0] = r[0]; bfr[2 * nf2][1] = r[1];
                bfr[2 * nf2 + 1][0] = r[2]; bfr[2 * nf2 + 1][1] = r[3];
            }
#pragma unroll
            for (int nf = 0; nf < NFRAG; nf++)
#pragma unroll
                for (int mf = 0; mf < MFRAG; mf++)
                    mma_f16(acc[mf][nf], afr[mf], bfr[nf]);
        }

        if (tt + 1 < NTILES) {
            store_tile(cur ^ 1);        // store into the other buffer (no conflict with reads)
            __syncthreads();            // one barrier per tile
        }
    }

#pragma unroll
    for (int mf = 0; mf < MFRAG; mf++) {
#pragma unroll
        for (int nf = 0; nf < NFRAG; nf++) {
            int r = rbase + m0 + mf * 16 + g;
            int c = n0 + nf * 8 + 2 * t;
            __half* C = (c < NH) ? C1 : C2;
            int cc = (c < NH) ? c : c - NH;
            if (r < n) {
                __half2 h = __floats2half2_rn(acc[mf][nf][0], acc[mf][nf][1]);
                *reinterpret_cast<__half2*>(&C[(size_t)r * NH + cc]) = h;
            }
            if (r + 8 < n) {
                __half2 h = __floats2half2_rn(acc[mf][nf][2], acc[mf][nf][3]);
                *reinterpret_cast<__half2*>(&C[(size_t)(r + 8) * NH + cc]) = h;
            }
        }
    }
}

// ---------------- layer-1 aggregation: warp/node, 128 feats fp16, shfl indices (R7) ----------------
__global__ void k_agg1(const float* __restrict__ b1, int n) {
    int gwarp = (blockIdx.x * blockDim.x + threadIdx.x) >> 5;
    int lane = threadIdx.x & 31;
    if (gwarp >= n) return;
    const int v = gwarp;
    const int cnt0 = g_cnt[v];
    const int cnt = cnt0 < CAP ? cnt0 : CAP;
    const size_t base = (size_t)v * CAP;
    const uint2* XN2 = reinterpret_cast<const uint2*>(g_XNh);

    uint2 ps = XN2[(size_t)v * 32 + lane];   // self
    float2 a01 = __half22float2(reinterpret_cast<__half2&>(ps.x));
    float2 a23 = __half22float2(reinterpret_cast<__half2&>(ps.y));
    float2 c01 = make_float2(0.f, 0.f), c23 = make_float2(0.f, 0.f);

    const int cf = cnt < 32 ? cnt : 32;
    int sidx = (lane < cf) ? g_slots[base + lane] : 0;
    int e = 0;
    for (; e + 4 <= cf; e += 4) {
        int s0 = __shfl_sync(0xffffffffu, sidx, e + 0);
        int s1 = __shfl_sync(0xffffffffu, sidx, e + 1);
        int s2 = __shfl_sync(0xffffffffu, sidx, e + 2);
        int s3 = __shfl_sync(0xffffffffu, sidx, e + 3);
        uint2 p0 = XN2[(size_t)s0 * 32 + lane];
        uint2 p1 = XN2[(size_t)s1 * 32 + lane];
        uint2 p2 = XN2[(size_t)s2 * 32 + lane];
        uint2 p3 = XN2[(size_t)s3 * 32 + lane];
        __half2 hx0 = __hadd2(reinterpret_cast<__half2&>(p0.x), reinterpret_cast<__half2&>(p1.x));
        __half2 hy0 = __hadd2(reinterpret_cast<__half2&>(p0.y), reinterpret_cast<__half2&>(p1.y));
        __half2 hx1 = __hadd2(reinterpret_cast<__half2&>(p2.x), reinterpret_cast<__half2&>(p3.x));
        __half2 hy1 = __hadd2(reinterpret_cast<__half2&>(p2.y), reinterpret_cast<__half2&>(p3.y));
        addf32x2(a01, __half22float2(hx0)); addf32x2(a23, __half22float2(hy0));
        addf32x2(c01, __half22float2(hx1)); addf32x2(c23, __half22float2(hy1));
    }
    for (; e < cf; e++) {
        int s = __shfl_sync(0xffffffffu, sidx, e);
        uint2 p = XN2[(size_t)s * 32 + lane];
        addf32x2(a01, __half22float2(reinterpret_cast<__half2&>(p.x)));
        addf32x2(a23, __half22float2(reinterpret_cast<__half2&>(p.y)));
    }
    for (; e < cnt; e++) {   // rare tail (deg > 32)
        int s = g_slots[base + e];
        uint2 p = XN2[(size_t)s * 32 + lane];
        addf32x2(a01, __half22float2(reinterpret_cast<__half2&>(p.x)));
        addf32x2(a23, __half22float2(reinterpret_cast<__half2&>(p.y)));
    }
    addf32x2(a01, c01); addf32x2(a23, c23);

    float inv = 1.0f / (float)(cnt0 + 1);
    uint2 xsp = reinterpret_cast<const uint2*>(g_XSh)[(size_t)v * 32 + lane];
    float2 xs01 = __half22float2(reinterpret_cast<__half2&>(xsp.x));
    float2 xs23 = __half22float2(reinterpret_cast<__half2&>(xsp.y));
    float4 bb = reinterpret_cast<const float4*>(b1)[lane];
    float hx = fmaxf(xs01.x + a01.x * inv + bb.x, 0.f);
    float hy = fmaxf(xs01.y + a01.y * inv + bb.y, 0.f);
    float hz = fmaxf(xs23.x + a23.x * inv + bb.z, 0.f);
    float hw = fmaxf(xs23.y + a23.y * inv + bb.w, 0.f);
    __half2 o0 = __floats2half2_rn(hx, hy);
    __half2 o1 = __floats2half2_rn(hz, hw);
    uint2 o = make_uint2(reinterpret_cast<uint32_t&>(o0), reinterpret_cast<uint32_t&>(o1));
    reinterpret_cast<uint2*>(g_Hh)[(size_t)v * 32 + lane] = o;
}

// ---------------- layer-2 aggregation: warp/node, 64 feats fp16 (R7) ----------------
__global__ void k_agg2(const float* __restrict__ b2, float* __restrict__ out, int n) {
    int gwarp = (blockIdx.x * blockDim.x + threadIdx.x) >> 5;
    int lane = threadIdx.x & 31;
    if (gwarp >= n) return;
    const int v = gwarp;
    const int cnt0 = g_cnt[v];
    const int cnt = cnt0 < CAP ? cnt0 : CAP;
    const size_t base = (size_t)v * CAP;
    const uint32_t* HN1 = reinterpret_cast<const uint32_t*>(g_HNh);

    uint32_t ps = HN1[(size_t)v * 32 + lane];
    float2 acc = __half22float2(reinterpret_cast<__half2&>(ps));
    float2 acc2 = make_float2(0.f, 0.f);

    const int cf = cnt < 32 ? cnt : 32;
    int sidx = (lane < cf) ? g_slots[base + lane] : 0;
    int e = 0;
    for (; e + 4 <= cf; e += 4) {
        int s0 = __shfl_sync(0xffffffffu, sidx, e + 0);
        int s1 = __shfl_sync(0xffffffffu, sidx, e + 1);
        int s2 = __shfl_sync(0xffffffffu, sidx, e + 2);
        int s3 = __shfl_sync(0xffffffffu, sidx, e + 3);
        uint32_t p0 = HN1[(size_t)s0 * 32 + lane];
        uint32_t p1 = HN1[(size_t)s1 * 32 + lane];
        uint32_t p2 = HN1[(size_t)s2 * 32 + lane];
        uint32_t p3 = HN1[(size_t)s3 * 32 + lane];
        __half2 h0 = __hadd2(reinterpret_cast<__half2&>(p0), reinterpret_cast<__half2&>(p1));
        __half2 h1 = __hadd2(reinterpret_cast<__half2&>(p2), reinterpret_cast<__half2&>(p3));
        addf32x2(acc, __half22float2(h0));
        addf32x2(acc2, __half22float2(h1));
    }
    for (; e < cf; e++) {
        int s = __shfl_sync(0xffffffffu, sidx, e);
        uint32_t p = HN1[(size_t)s * 32 + lane];
        addf32x2(acc, __half22float2(reinterpret_cast<__half2&>(p)));
    }
    for (; e < cnt; e++) {
        int s = g_slots[base + e];
        uint32_t p = HN1[(size_t)s * 32 + lane];
        addf32x2(acc, __half22float2(reinterpret_cast<__half2&>(p)));
    }
    addf32x2(acc, acc2);

    float inv = 1.0f / (float)(cnt0 + 1);
    uint32_t hsp = reinterpret_cast<const uint32_t*>(g_HSh)[(size_t)v * 32 + lane];
    float2 hs = __half22float2(reinterpret_cast<__half2&>(hsp));
    float2 bb = reinterpret_cast<const float2*>(b2)[lane];
    float2 o;
    o.x = hs.x + acc.x * inv + bb.x;
    o.y = hs.y + acc.y * inv + bb.y;
    reinterpret_cast<float2*>(out)[(size_t)v * 32 + lane] = o;
}

// ---------------- launch ----------------
extern "C" void kernel_launch(void* const* d_in, const int* in_sizes, int n_in,
                              void* d_out, int out_size) {
    const float* x       = (const float*)d_in[0];
    const int*   src     = (const int*)d_in[1];
    const int*   dst     = (const int*)d_in[2];
    const float* W_self1 = (const float*)d_in[3];
    const float* W_neigh1= (const float*)d_in[4];
    const float* b1      = (const float*)d_in[5];
    const float* W_self2 = (const float*)d_in[6];
    const float* W_neigh2= (const float*)d_in[7];
    const float* b2      = (const float*)d_in[8];
    float* out = (float*)d_out;

    const int n = in_sizes[0] / 128;
    const int e = in_sizes[1];

    __half *XSh, *XNh, *Hh, *HSh, *HNh, *Wt1, *Wt2;
    int* cnt;
    cudaGetSymbolAddress((void**)&XSh, g_XSh);
    cudaGetSymbolAddress((void**)&XNh, g_XNh);
    cudaGetSymbolAddress((void**)&Hh,  g_Hh);
    cudaGetSymbolAddress((void**)&HSh, g_HSh);
    cudaGetSymbolAddress((void**)&HNh, g_HNh);
    cudaGetSymbolAddress((void**)&Wt1, g_Wt1);
    cudaGetSymbolAddress((void**)&Wt2, g_Wt2);
    cudaGetSymbolAddress((void**)&cnt, g_cnt);

    constexpr int S32 = 20;
    const int SMEM1 = 2 * (128 * S32 + 256 * S32) * 4;   // 61,440 B
    const int SMEM2 = 2 * (128 * S32 + 128 * S32) * 4;   // 40,960 B

    // One-time host resources (host-side only; device work per call unchanged).
    static cudaStream_t s2 = nullptr;
    static cudaEvent_t evRoot = nullptr, evScat = nullptr;
    if (!s2) {
        cudaStreamCreateWithFlags(&s2, cudaStreamNonBlocking);
        cudaEventCreateWithFlags(&evRoot, cudaEventDisableTiming);
        cudaEventCreateWithFlags(&evScat, cudaEventDisableTiming);
        cudaFuncSetAttribute((const void*)k_gemm_f16<256, 512, 4, 2, float>,
                             cudaFuncAttributeMaxDynamicSharedMemorySize, SMEM1);
        cudaFuncSetAttribute((const void*)k_gemm_f16<128, 256, 4, 2, __half>,
                             cudaFuncAttributeMaxDynamicSharedMemorySize, SMEM2);
    }

    // Fork: branch A (s2) = memset + scatter; branch B (default) = prep + gemm1.
    cudaEventRecord(evRoot, 0);
    cudaStreamWaitEvent(s2, evRoot, 0);

    cudaMemsetAsync(cnt, 0, (size_t)n * sizeof(int), s2);
    k_scatter<<<1024, 256, 0, s2>>>(src, dst, e);
    cudaEventRecord(evScat, s2);

    k_prep<<<192, 256>>>(W_self1, W_neigh1, W_self2, W_neigh2);
    int gblocks = (n + 127) / 128;
    k_gemm_f16<256, 512, 4, 2, float><<<gblocks, 512, SMEM1>>>(x, Wt1, XSh, XNh, n);

    // Join: agg1 needs both branches.
    cudaStreamWaitEvent(0, evScat, 0);

    int ablocks = (n + 7) / 8;
    k_agg1<<<ablocks, 256>>>(b1, n);

    k_gemm_f16<128, 256, 4, 2, __half><<<gblocks, 256, SMEM2>>>(Hh, Wt2, HSh, HNh, n);

    k_agg2<<<ablocks, 256>>>(b2, out, n);
}

// round 16
// speedup vs baseline: 1.0086x; 1.0086x over previous
#include <cuda_runtime.h>
#include <cuda_fp16.h>
#include <stdint.h>

#define NMAX 100000
#define CAP  64   // max in-degree bucket (Poisson(10): P(deg>64) ~ 1e-40)

// ---------------- scratch (static device globals; no allocation) ----------------
__device__ int g_cnt[NMAX];
__device__ int g_slots[(size_t)NMAX * CAP];
__device__ __half g_XSh[(size_t)NMAX * 128];
__device__ __half g_XNh[(size_t)NMAX * 128];
__device__ __half g_Hh [(size_t)NMAX * 128];
__device__ __half g_HSh[(size_t)NMAX * 64];
__device__ __half g_HNh[(size_t)NMAX * 64];
__device__ __half g_Wt1[256 * 128];
__device__ __half g_Wt2[128 * 128];

__device__ __forceinline__ void addf32x2(float2& a, float2 b) {
    unsigned long long ua = reinterpret_cast<unsigned long long&>(a);
    unsigned long long ub = reinterpret_cast<unsigned long long&>(b);
    asm("add.rn.f32x2 %0, %0, %1;" : "+l"(ua) : "l"(ub));
    a = reinterpret_cast<float2&>(ua);
}
__device__ __forceinline__ uint32_t smem_u32(const void* p) {
    uint32_t a;
    asm("{ .reg .u64 t; cvta.to.shared.u64 t, %1; cvt.u32.u64 %0, t; }" : "=r"(a) : "l"(p));
    return a;
}
__device__ __forceinline__ void ldsm_x4(uint32_t r[4], uint32_t addr) {
    asm volatile("ldmatrix.sync.aligned.m8n8.x4.shared.b16 {%0,%1,%2,%3}, [%4];"
                 : "=r"(r[0]), "=r"(r[1]), "=r"(r[2]), "=r"(r[3]) : "r"(addr));
}

// ---------------- prep: both weight transposes ----------------
__global__ void k_prep(const float* __restrict__ Ws1, const float* __restrict__ Wn1,
                       const float* __restrict__ Ws2, const float* __restrict__ Wn2) {
    int b = blockIdx.x, tid = threadIdx.x;
    if (b < 128) {                                // Wt1: 256*128 elems
        int idx = b * 256 + tid;
        int k = idx >> 8, nn = idx & 255;
        float v = (nn < 128) ? Ws1[(size_t)k * 128 + nn] : Wn1[(size_t)k * 128 + (nn - 128)];
        g_Wt1[(size_t)nn * 128 + k] = __float2half(v);
    } else {                                      // Wt2: 128*128 elems
        int idx = (b - 128) * 256 + tid;
        int k = idx >> 7, nn = idx & 127;
        float v = (nn < 64) ? Ws2[(size_t)k * 64 + nn] : Wn2[(size_t)k * 64 + (nn - 64)];
        g_Wt2[(size_t)nn * 128 + k] = __float2half(v);
    }
}

// ---------------- scatter: 4 edges per thread via int4 ----------------
__global__ void k_scatter(const int* __restrict__ src, const int* __restrict__ dst, int e) {
    const int nq = e >> 2;
    const int4* s4 = reinterpret_cast<const int4*>(src);
    const int4* d4 = reinterpret_cast<const int4*>(dst);
    for (int q = blockIdx.x * blockDim.x + threadIdx.x; q < nq; q += gridDim.x * blockDim.x) {
        int4 s = s4[q];
        int4 d = d4[q];
        int p;
        p = atomicAdd(&g_cnt[d.x], 1); if (p < CAP) g_slots[(size_t)d.x * CAP + p] = s.x;
        p = atomicAdd(&g_cnt[d.y], 1); if (p < CAP) g_slots[(size_t)d.y * CAP + p] = s.y;
        p = atomicAdd(&g_cnt[d.z], 1); if (p < CAP) g_slots[(size_t)d.z * CAP + p] = s.z;
        p = atomicAdd(&g_cnt[d.w], 1); if (p < CAP) g_slots[(size_t)d.w * CAP + p] = s.w;
    }
    if (blockIdx.x == 0 && threadIdx.x == 0) {
        for (int i = nq * 4; i < e; i++) {
            int d = dst[i];
            int p = atomicAdd(&g_cnt[d], 1);
            if (p < CAP) g_slots[(size_t)d * CAP + p] = src[i];
        }
    }
}

// ---------------- fp16 mma.sync GEMM with ldmatrix, double-buffered smem ----------------
__device__ __forceinline__ void mma_f16(float c[4], const uint32_t a[4], const uint32_t b[2]) {
    asm volatile(
        "mma.sync.aligned.m16n8k16.row.col.f32.f16.f16.f32 "
        "{%0,%1,%2,%3}, {%4,%5,%6,%7}, {%8,%9}, {%0,%1,%2,%3};\n"
        : "+f"(c[0]), "+f"(c[1]), "+f"(c[2]), "+f"(c[3])
        : "r"(a[0]), "r"(a[1]), "r"(a[2]), "r"(a[3]), "r"(b[0]), "r"(b[1]));
}

// [C1h|C2h] = A[n x 128] @ Wt^T. CTA 128(M) x NT(N), K=128, BK=32, 2-stage smem pipeline.
template <int NT, int THREADS, int WM, int MFRAG, typename TA>
__global__ void __launch_bounds__(THREADS, 1)
k_gemm_f16(const TA* __restrict__ A, const __half* __restrict__ Wt,
           __half* __restrict__ C1, __half* __restrict__ C2, int n) {
    constexpr int BK = 32;
    constexpr int NH = NT / 2;
    constexpr int NWARPS = THREADS / 32;
    constexpr int WN = NWARPS / WM;
    constexpr int NFRAG = NT / (WN * 8);
    constexpr int S32 = 20;
    constexpr int PA = 128 * BK / 8 / THREADS;
    constexpr int PB = NT * BK / 8 / THREADS;
    constexpr int NTILES = 128 / BK;
    constexpr int A_WORDS = 128 * S32;
    constexpr int B_WORDS = NT * S32;

    extern __shared__ uint32_t sm[];
    uint32_t* As = sm;
    uint32_t* Bs = sm + 2 * A_WORDS;

    const int tid = threadIdx.x;
    const int lane = tid & 31, wid = tid >> 5;
    const int wm = wid % WM, wn = wid / WM;
    const int m0 = wm * (MFRAG * 16);
    const int n0 = wn * (NFRAG * 8);
    const int g = lane >> 2, t = lane & 3;
    const int rbase = blockIdx.x * 128;

    const uint32_t as_b = smem_u32(As), bs_b = smem_u32(Bs);
    const int aRow = m0 + ((lane >> 3) & 1) * 8 + (lane & 7);
    const int aK = (lane >> 4) * 16;
    const uint32_t aAddr = as_b + aRow * 80 + aK;
    const int bRow = n0 + (lane >> 4) * 8 + (lane & 7);
    const int bK = ((lane >> 3) & 1) * 16;
    const uint32_t bAddr = bs_b + bRow * 80 + bK;

    float acc[MFRAG][NFRAG][4];
#pragma unroll
    for (int mf = 0; mf < MFRAG; mf++)
#pragma unroll
        for (int nf = 0; nf < NFRAG; nf++)
#pragma unroll
            for (int j = 0; j < 4; j++) acc[mf][nf][j] = 0.f;

    uint4 pa[PA], pb[PB];

    auto load_a = [&](int kk) {
#pragma unroll
        for (int i = 0; i < PA; i++) {
            int idx = tid + i * THREADS;
            int row = idx >> 2, kg = idx & 3;
            int r = rbase + row;
            if (sizeof(TA) == 4) {
                const float* Af = reinterpret_cast<const float*>(A);
                float4 f0, f1;
                if (r < n) {
                    f0 = *reinterpret_cast<const float4*>(&Af[(size_t)r * 128 + kk + kg * 8]);
                    f1 = *reinterpret_cast<const float4*>(&Af[(size_t)r * 128 + kk + kg * 8 + 4]);
                } else {
                    f0 = f1 = make_float4(0.f, 0.f, 0.f, 0.f);
                }
                __half2 h0 = __floats2half2_rn(f0.x, f0.y);
                __half2 h1 = __floats2half2_rn(f0.z, f0.w);
                __half2 h2 = __floats2half2_rn(f1.x, f1.y);
                __half2 h3 = __floats2half2_rn(f1.z, f1.w);
                pa[i] = make_uint4(reinterpret_cast<uint32_t&>(h0), reinterpret_cast<uint32_t&>(h1),
                                   reinterpret_cast<uint32_t&>(h2), reinterpret_cast<uint32_t&>(h3));
            } else {
                const __half* Ah = reinterpret_cast<const __half*>(A);
                pa[i] = (r < n) ? *reinterpret_cast<const uint4*>(&Ah[(size_t)r * 128 + kk + kg * 8])
                                : make_uint4(0u, 0u, 0u, 0u);
            }
        }
    };
    auto load_b = [&](int kk) {
#pragma unroll
        for (int i = 0; i < PB; i++) {
            int idx = tid + i * THREADS;
            int nn = idx >> 2, kg = idx & 3;
            pb[i] = *reinterpret_cast<const uint4*>(&Wt[(size_t)nn * 128 + kk + kg * 8]);
        }
    };
    auto store_tile = [&](int buf) {
#pragma unroll
        for (int i = 0; i < PA; i++) {
            int idx = tid + i * THREADS;
            int row = idx >> 2, kg = idx & 3;
            *reinterpret_cast<uint4*>(&As[buf * A_WORDS + row * S32 + kg * 4]) = pa[i];
        }
#pragma unroll
        for (int i = 0; i < PB; i++) {
            int idx = tid + i * THREADS;
            int nn = idx >> 2, kg = idx & 3;
            *reinterpret_cast<uint4*>(&Bs[buf * B_WORDS + nn * S32 + kg * 4]) = pb[i];
        }
    };

    load_a(0);
    load_b(0);
    store_tile(0);
    __syncthreads();

    for (int tt = 0; tt < NTILES; tt++) {
        const int cur = tt & 1;
        const uint32_t aOff = cur * (A_WORDS * 4);
        const uint32_t bOff = cur * (B_WORDS * 4);

        if (tt + 1 < NTILES) {
            load_a((tt + 1) * BK);
            load_b((tt + 1) * BK);
        }

#pragma unroll
        for (int ks = 0; ks < BK; ks += 16) {
            uint32_t afr[MFRAG][4];
#pragma unroll
            for (int mf = 0; mf < MFRAG; mf++)
                ldsm_x4(afr[mf], aAddr + aOff + mf * 16 * 80 + ks * 2);
            uint32_t bfr[NFRAG][2];
#pragma unroll
            for (int nf2 = 0; nf2 < NFRAG / 2; nf2++) {
                uint32_t r[4];
                ldsm_x4(r, bAddr + bOff + nf2 * 16 * 80 + ks * 2);
                bfr[2 * nf2][0] = r[0]; bfr[2 * nf2][1] = r[1];
                bfr[2 * nf2 + 1][0] = r[2]; bfr[2 * nf2 + 1][1] = r[3];
            }
#pragma unroll
            for (int nf = 0; nf < NFRAG; nf++)
#pragma unroll
                for (int mf = 0; mf < MFRAG; mf++)
                    mma_f16(acc[mf][nf], afr[mf], bfr[nf]);
        }

        if (tt + 1 < NTILES) {
            store_tile(cur ^ 1);
            __syncthreads();
        }
    }

#pragma unroll
    for (int mf = 0; mf < MFRAG; mf++) {
#pragma unroll
        for (int nf = 0; nf < NFRAG; nf++) {
            int r = rbase + m0 + mf * 16 + g;
            int c = n0 + nf * 8 + 2 * t;
            __half* C = (c < NH) ? C1 : C2;
            int cc = (c < NH) ? c : c - NH;
            if (r < n) {
                __half2 h = __floats2half2_rn(acc[mf][nf][0], acc[mf][nf][1]);
                *reinterpret_cast<__half2*>(&C[(size_t)r * NH + cc]) = h;
            }
            if (r + 8 < n) {
                __half2 h = __floats2half2_rn(acc[mf][nf][2], acc[mf][nf][3]);
                *reinterpret_cast<__half2*>(&C[(size_t)(r + 8) * NH + cc]) = h;
            }
        }
    }
}

// ---------------- layer-1 aggregation: warp/node, fp16 tree depth 2, 32-bit addressing ----------------
__global__ void k_agg1(const float* __restrict__ b1, int n) {
    int gwarp = (blockIdx.x * blockDim.x + threadIdx.x) >> 5;
    int lane = threadIdx.x & 31;
    if (gwarp >= n) return;
    const int v = gwarp;
    const int cnt0 = g_cnt[v];
    const int cnt = cnt0 < CAP ? cnt0 : CAP;
    const size_t base = (size_t)v * CAP;
    const uint2* XN2 = reinterpret_cast<const uint2*>(g_XNh);

    uint2 ps = XN2[(unsigned)(v << 5) + lane];   // self
    float2 a01 = __half22float2(reinterpret_cast<__half2&>(ps.x));
    float2 a23 = __half22float2(reinterpret_cast<__half2&>(ps.y));

    const int cf = cnt < 32 ? cnt : 32;
    int sidx = (lane < cf) ? g_slots[base + lane] : 0;
    int e = 0;
    for (; e + 4 <= cf; e += 4) {
        unsigned s0 = (unsigned)__shfl_sync(0xffffffffu, sidx, e + 0) << 5;
        unsigned s1 = (unsigned)__shfl_sync(0xffffffffu, sidx, e + 1) << 5;
        unsigned s2 = (unsigned)__shfl_sync(0xffffffffu, sidx, e + 2) << 5;
        unsigned s3 = (unsigned)__shfl_sync(0xffffffffu, sidx, e + 3) << 5;
        uint2 p0 = XN2[s0 + lane];
        uint2 p1 = XN2[s1 + lane];
        uint2 p2 = XN2[s2 + lane];
        uint2 p3 = XN2[s3 + lane];
        // 2-level fp16 tree, then one fp32 promotion
        __half2 hx = __hadd2(__hadd2(reinterpret_cast<__half2&>(p0.x), reinterpret_cast<__half2&>(p1.x)),
                             __hadd2(reinterpret_cast<__half2&>(p2.x), reinterpret_cast<__half2&>(p3.x)));
        __half2 hy = __hadd2(__hadd2(reinterpret_cast<__half2&>(p0.y), reinterpret_cast<__half2&>(p1.y)),
                             __hadd2(reinterpret_cast<__half2&>(p2.y), reinterpret_cast<__half2&>(p3.y)));
        addf32x2(a01, __half22float2(hx));
        addf32x2(a23, __half22float2(hy));
    }
    for (; e < cf; e++) {
        unsigned s = (unsigned)__shfl_sync(0xffffffffu, sidx, e) << 5;
        uint2 p = XN2[s + lane];
        addf32x2(a01, __half22float2(reinterpret_cast<__half2&>(p.x)));
        addf32x2(a23, __half22float2(reinterpret_cast<__half2&>(p.y)));
    }
    for (; e < cnt; e++) {   // rare tail (deg > 32)
        unsigned s = (unsigned)g_slots[base + e] << 5;
        uint2 p = XN2[s + lane];
        addf32x2(a01, __half22float2(reinterpret_cast<__half2&>(p.x)));
        addf32x2(a23, __half22float2(reinterpret_cast<__half2&>(p.y)));
    }

    float inv = 1.0f / (float)(cnt0 + 1);
    uint2 xsp = reinterpret_cast<const uint2*>(g_XSh)[(unsigned)(v << 5) + lane];
    float2 xs01 = __half22float2(reinterpret_cast<__half2&>(xsp.x));
    float2 xs23 = __half22float2(reinterpret_cast<__half2&>(xsp.y));
    float4 bb = reinterpret_cast<const float4*>(b1)[lane];
    float hx = fmaxf(xs01.x + a01.x * inv + bb.x, 0.f);
    float hy = fmaxf(xs01.y + a01.y * inv + bb.y, 0.f);
    float hz = fmaxf(xs23.x + a23.x * inv + bb.z, 0.f);
    float hw = fmaxf(xs23.y + a23.y * inv + bb.w, 0.f);
    __half2 o0 = __floats2half2_rn(hx, hy);
    __half2 o1 = __floats2half2_rn(hz, hw);
    uint2 o = make_uint2(reinterpret_cast<uint32_t&>(o0), reinterpret_cast<uint32_t&>(o1));
    reinterpret_cast<uint2*>(g_Hh)[(unsigned)(v << 5) + lane] = o;
}

// ---------------- layer-2 aggregation: warp/node, fp16 tree depth 2, 32-bit addressing ----------------
__global__ void k_agg2(const float* __restrict__ b2, float* __restrict__ out, int n) {
    int gwarp = (blockIdx.x * blockDim.x + threadIdx.x) >> 5;
    int lane = threadIdx.x & 31;
    if (gwarp >= n) return;
    const int v = gwarp;
    const int cnt0 = g_cnt[v];
    const int cnt = cnt0 < CAP ? cnt0 : CAP;
    const size_t base = (size_t)v * CAP;
    const uint32_t* HN1 = reinterpret_cast<const uint32_t*>(g_HNh);

    uint32_t ps = HN1[(unsigned)(v << 5) + lane];
    float2 acc = __half22float2(reinterpret_cast<__half2&>(ps));

    const int cf = cnt < 32 ? cnt : 32;
    int sidx = (lane < cf) ? g_slots[base + lane] : 0;
    int e = 0;
    for (; e + 4 <= cf; e += 4) {
        unsigned s0 = (unsigned)__shfl_sync(0xffffffffu, sidx, e + 0) << 5;
        unsigned s1 = (unsigned)__shfl_sync(0xffffffffu, sidx, e + 1) << 5;
        unsigned s2 = (unsigned)__shfl_sync(0xffffffffu, sidx, e + 2) << 5;
        unsigned s3 = (unsigned)__shfl_sync(0xffffffffu, sidx, e + 3) << 5;
        uint32_t p0 = HN1[s0 + lane];
        uint32_t p1 = HN1[s1 + lane];
        uint32_t p2 = HN1[s2 + lane];
        uint32_t p3 = HN1[s3 + lane];
        __half2 h = __hadd2(__hadd2(reinterpret_cast<__half2&>(p0), reinterpret_cast<__half2&>(p1)),
                            __hadd2(reinterpret_cast<__half2&>(p2), reinterpret_cast<__half2&>(p3)));
        addf32x2(acc, __half22float2(h));
    }
    for (; e < cf; e++) {
        unsigned s = (unsigned)__shfl_sync(0xffffffffu, sidx, e) << 5;
        uint32_t p = HN1[s + lane];
        addf32x2(acc, __half22float2(reinterpret_cast<__half2&>(p)));
    }
    for (; e < cnt; e++) {
        unsigned s = (unsigned)g_slots[base + e] << 5;
        uint32_t p = HN1[s + lane];
        addf32x2(acc, __half22float2(reinterpret_cast<__half2&>(p)));
    }

    float inv = 1.0f / (float)(cnt0 + 1);
    uint32_t hsp = reinterpret_cast<const uint32_t*>(g_HSh)[(unsigned)(v << 5) + lane];
    float2 hs = __half22float2(reinterpret_cast<__half2&>(hsp));
    float2 bb = reinterpret_cast<const float2*>(b2)[lane];
    float2 o;
    o.x = hs.x + acc.x * inv + bb.x;
    o.y = hs.y + acc.y * inv + bb.y;
    reinterpret_cast<float2*>(out)[(unsigned)(v << 5) + lane] = o;
}

// ---------------- launch ----------------
extern "C" void kernel_launch(void* const* d_in, const int* in_sizes, int n_in,
                              void* d_out, int out_size) {
    const float* x       = (const float*)d_in[0];
    const int*   src     = (const int*)d_in[1];
    const int*   dst     = (const int*)d_in[2];
    const float* W_self1 = (const float*)d_in[3];
    const float* W_neigh1= (const float*)d_in[4];
    const float* b1      = (const float*)d_in[5];
    const float* W_self2 = (const float*)d_in[6];
    const float* W_neigh2= (const float*)d_in[7];
    const float* b2      = (const float*)d_in[8];
    float* out = (float*)d_out;

    const int n = in_sizes[0] / 128;
    const int e = in_sizes[1];

    __half *XSh, *XNh, *Hh, *HSh, *HNh, *Wt1, *Wt2;
    int* cnt;
    cudaGetSymbolAddress((void**)&XSh, g_XSh);
    cudaGetSymbolAddress((void**)&XNh, g_XNh);
    cudaGetSymbolAddress((void**)&Hh,  g_Hh);
    cudaGetSymbolAddress((void**)&HSh, g_HSh);
    cudaGetSymbolAddress((void**)&HNh, g_HNh);
    cudaGetSymbolAddress((void**)&Wt1, g_Wt1);
    cudaGetSymbolAddress((void**)&Wt2, g_Wt2);
    cudaGetSymbolAddress((void**)&cnt, g_cnt);

    constexpr int S32 = 20;
    const int SMEM1 = 2 * (128 * S32 + 256 * S32) * 4;   // 61,440 B
    const int SMEM2 = 2 * (128 * S32 + 128 * S32) * 4;   // 40,960 B

    static cudaStream_t s2 = nullptr;
    static cudaEvent_t evRoot = nullptr, evScat = nullptr;
    if (!s2) {
        cudaStreamCreateWithFlags(&s2, cudaStreamNonBlocking);
        cudaEventCreateWithFlags(&evRoot, cudaEventDisableTiming);
        cudaEventCreateWithFlags(&evScat, cudaEventDisableTiming);
        cudaFuncSetAttribute((const void*)k_gemm_f16<256, 512, 4, 2, float>,
                             cudaFuncAttributeMaxDynamicSharedMemorySize, SMEM1);
        cudaFuncSetAttribute((const void*)k_gemm_f16<128, 256, 4, 2, __half>,
                             cudaFuncAttributeMaxDynamicSharedMemorySize, SMEM2);
    }

    // Fork: branch A (s2) = memset + scatter; branch B (default) = prep + gemm1.
    cudaEventRecord(evRoot, 0);
    cudaStreamWaitEvent(s2, evRoot, 0);

    cudaMemsetAsync(cnt, 0, (size_t)n * sizeof(int), s2);
    k_scatter<<<1024, 256, 0, s2>>>(src, dst, e);
    cudaEventRecord(evScat, s2);

    k_prep<<<192, 256>>>(W_self1, W_neigh1, W_self2, W_neigh2);
    int gblocks = (n + 127) / 128;
    k_gemm_f16<256, 512, 4, 2, float><<<gblocks, 512, SMEM1>>>(x, Wt1, XSh, XNh, n);

    // Join: agg1 needs both branches.
    cudaStreamWaitEvent(0, evScat, 0);

    int ablocks = (n + 7) / 8;
    k_agg1<<<ablocks, 256>>>(b1, n);

    k_gemm_f16<128, 256, 4, 2, __half><<<gblocks, 256, SMEM2>>>(Hh, Wt2, HSh, HNh, n);

    k_agg2<<<ablocks, 256>>>(b2, out, n);
}